// round 6
// baseline (speedup 1.0000x reference)
#include <cuda_runtime.h>
#include <math.h>
#include <stddef.h>
#include <stdint.h>

#define BATCH 8
#define NT 1024
#define TD 128
#define HID 512
#define NH 8
#define HD 64

// ---------------- helpers ----------------
__device__ __forceinline__ float tf32r(float x){
    uint32_t u; asm("cvt.rna.tf32.f32 %0, %1;" : "=r"(u) : "f"(x));
    return __uint_as_float(u);
}
__device__ __forceinline__ void mma_tf32(float* c,
    uint32_t a0, uint32_t a1, uint32_t a2, uint32_t a3,
    uint32_t b0, uint32_t b1){
    asm("mma.sync.aligned.m16n8k8.row.col.f32.tf32.tf32.f32 "
        "{%0,%1,%2,%3}, {%4,%5,%6,%7}, {%8,%9}, {%0,%1,%2,%3};"
        : "+f"(c[0]), "+f"(c[1]), "+f"(c[2]), "+f"(c[3])
        : "r"(a0), "r"(a1), "r"(a2), "r"(a3), "r"(b0), "r"(b1));
}

// ---------------- device scratch (static; no allocation) ----------------
__device__ unsigned g_tmax_u;                 // zero at module load; atomicMax idempotent across replays
__device__ float g_weff[TD * HID];            // struct_W^T @ W0cat
__device__ float g_beff[HID];                 // struct_b @ W0cat
__device__ float g_h[BATCH * NT * HID];       // h per (b,n,[h*64+d])
__device__ float g_node[BATCH * NT * HID];    // GAT layer output
__device__ float g_esrc[BATCH * NH * NT];
__device__ float g_edst[BATCH * NH * NT];

// ---------------- tmax (idempotent: inputs constant across replays) ----------------
__global__ void k_tmax(const float4* __restrict__ t, int n4) {
    float m = 0.f;
    for (int i = blockIdx.x * blockDim.x + threadIdx.x; i < n4; i += gridDim.x * blockDim.x) {
        float4 v = t[i];
        m = fmaxf(m, fmaxf(fmaxf(v.x, v.y), fmaxf(v.z, v.w)));
    }
#pragma unroll
    for (int s = 16; s; s >>= 1) m = fmaxf(m, __shfl_xor_sync(0xffffffffu, m, s));
    __shared__ float sm[8];
    if ((threadIdx.x & 31) == 0) sm[threadIdx.x >> 5] = m;
    __syncthreads();
    if (threadIdx.x == 0) {
        for (int w = 1; w < 8; w++) m = fmaxf(m, sm[w]);
        atomicMax(&g_tmax_u, __float_as_uint(m));  // positives: uint order == float order
    }
}

// ---------------- Weff = struct_W^T @ W0cat ; beff = struct_b @ W0cat ----------------
// sW [HID,TD] row-major; W0cat[k][hh*64+d] = gW0[hh*HID*HD + k*HD + d]
__global__ void k_weff(const float* __restrict__ sW, const float* __restrict__ sb,
                       const float* __restrict__ gW0,
                       float* __restrict__ weff, float* __restrict__ beff) {
    __shared__ float As[32][68];
    __shared__ float Bs[32][68];
    int t = threadIdx.x;
    int tx = t & 15, ty = t >> 4;
    int m0 = blockIdx.x * 64, n0 = blockIdx.y * 64;
    int hh = n0 >> 6;
    const float* B0 = gW0 + (size_t)hh * (HID * HD);
    float acc[4][4] = {};
    int bk = t >> 3, bnc = (t & 7) * 8;

    for (int kt = 0; kt < HID; kt += 32) {
        {   // A is K-major already: As[k][m] direct
            const float* ap = sW + (size_t)(kt + bk) * TD + m0 + bnc;
            *reinterpret_cast<float4*>(&As[bk][bnc])     = *reinterpret_cast<const float4*>(ap);
            *reinterpret_cast<float4*>(&As[bk][bnc + 4]) = *reinterpret_cast<const float4*>(ap + 4);
            const float* bp = B0 + (size_t)(kt + bk) * HD + bnc;
            *reinterpret_cast<float4*>(&Bs[bk][bnc])     = *reinterpret_cast<const float4*>(bp);
            *reinterpret_cast<float4*>(&Bs[bk][bnc + 4]) = *reinterpret_cast<const float4*>(bp + 4);
        }
        __syncthreads();
#pragma unroll
        for (int k = 0; k < 32; k++) {
            float4 a4 = *reinterpret_cast<const float4*>(&As[k][ty * 4]);
            float4 b4 = *reinterpret_cast<const float4*>(&Bs[k][tx * 4]);
            acc[0][0] += a4.x * b4.x; acc[0][1] += a4.x * b4.y; acc[0][2] += a4.x * b4.z; acc[0][3] += a4.x * b4.w;
            acc[1][0] += a4.y * b4.x; acc[1][1] += a4.y * b4.y; acc[1][2] += a4.y * b4.z; acc[1][3] += a4.y * b4.w;
            acc[2][0] += a4.z * b4.x; acc[2][1] += a4.z * b4.y; acc[2][2] += a4.z * b4.z; acc[2][3] += a4.z * b4.w;
            acc[3][0] += a4.w * b4.x; acc[3][1] += a4.w * b4.y; acc[3][2] += a4.w * b4.z; acc[3][3] += a4.w * b4.w;
        }
        __syncthreads();
    }
#pragma unroll
    for (int ii = 0; ii < 4; ii++) {
        float4 o;
        o.x = acc[ii][0]; o.y = acc[ii][1]; o.z = acc[ii][2]; o.w = acc[ii][3];
        *reinterpret_cast<float4*>(weff + (size_t)(m0 + ty * 4 + ii) * HID + n0 + tx * 4) = o;
    }
    if (blockIdx.x == 0 && t < 64) {
        float s = 0.f;
        for (int k = 0; k < HID; k++) s += sb[k] * B0[(size_t)k * HD + t];
        beff[n0 + t] = s;
    }
}

// ---------------- 64x64 fp32 GEMM (N=512) + fused e_src/e_dst epilogue ----------------
// bgat=0: B plain [K,512] row-major. bgat=1: B[k][hh*64+d] = Bg[hh*HID*HD + k*HD + d].
__global__ void k_gemmse(const float* __restrict__ A, const float* __restrict__ B,
                         float* __restrict__ C, const float* __restrict__ bias,
                         int K, int bgat, const float* __restrict__ ga,
                         float* __restrict__ esrc, float* __restrict__ edst) {
    __shared__ float As[32][68];
    __shared__ float Bs[32][68];
    int t = threadIdx.x;
    int tx = t & 15, ty = t >> 4;
    int m0 = blockIdx.x * 64, n0 = blockIdx.y * 64;
    int hh = n0 >> 6;
    float acc[4][4] = {};
    int ar = t >> 3, akc = (t & 7) * 4;
    int bk = t >> 3, bnc = (t & 7) * 8;
    const float* Bbase = bgat ? (B + (size_t)hh * (HID * HD)) : (B + n0);
    int bstride = bgat ? HD : HID;

    for (int kt = 0; kt < K; kt += 32) {
#pragma unroll
        for (int rr = 0; rr < 64; rr += 32) {
            float4 v = *reinterpret_cast<const float4*>(A + (size_t)(m0 + ar + rr) * K + kt + akc);
            As[akc + 0][ar + rr] = v.x;
            As[akc + 1][ar + rr] = v.y;
            As[akc + 2][ar + rr] = v.z;
            As[akc + 3][ar + rr] = v.w;
        }
        {
            const float* bp = Bbase + (size_t)(kt + bk) * bstride + bnc;
            *reinterpret_cast<float4*>(&Bs[bk][bnc])     = *reinterpret_cast<const float4*>(bp);
            *reinterpret_cast<float4*>(&Bs[bk][bnc + 4]) = *reinterpret_cast<const float4*>(bp + 4);
        }
        __syncthreads();
#pragma unroll
        for (int k = 0; k < 32; k++) {
            float4 a4 = *reinterpret_cast<const float4*>(&As[k][ty * 4]);
            float4 b4 = *reinterpret_cast<const float4*>(&Bs[k][tx * 4]);
            acc[0][0] += a4.x * b4.x; acc[0][1] += a4.x * b4.y; acc[0][2] += a4.x * b4.z; acc[0][3] += a4.x * b4.w;
            acc[1][0] += a4.y * b4.x; acc[1][1] += a4.y * b4.y; acc[1][2] += a4.y * b4.z; acc[1][3] += a4.y * b4.w;
            acc[2][0] += a4.z * b4.x; acc[2][1] += a4.z * b4.y; acc[2][2] += a4.z * b4.z; acc[2][3] += a4.z * b4.w;
            acc[3][0] += a4.w * b4.x; acc[3][1] += a4.w * b4.y; acc[3][2] += a4.w * b4.z; acc[3][3] += a4.w * b4.w;
        }
        __syncthreads();
    }
    if (bias) {
        float bx = bias[n0 + tx * 4 + 0], by = bias[n0 + tx * 4 + 1];
        float bz = bias[n0 + tx * 4 + 2], bw = bias[n0 + tx * 4 + 3];
#pragma unroll
        for (int ii = 0; ii < 4; ii++) {
            acc[ii][0] += bx; acc[ii][1] += by; acc[ii][2] += bz; acc[ii][3] += bw;
        }
    }
    // fused se: dot h-row (this head) with a_src/a_dst; reduce across tx (16 lanes)
    const float* gas = ga + (size_t)hh * 2 * HD;
    float as0 = gas[tx * 4 + 0], as1 = gas[tx * 4 + 1], as2 = gas[tx * 4 + 2], as3 = gas[tx * 4 + 3];
    float ad0 = gas[HD + tx * 4 + 0], ad1 = gas[HD + tx * 4 + 1], ad2 = gas[HD + tx * 4 + 2], ad3 = gas[HD + tx * 4 + 3];
#pragma unroll
    for (int ii = 0; ii < 4; ii++) {
        float ps = acc[ii][0] * as0 + acc[ii][1] * as1 + acc[ii][2] * as2 + acc[ii][3] * as3;
        float pd = acc[ii][0] * ad0 + acc[ii][1] * ad1 + acc[ii][2] * ad2 + acc[ii][3] * ad3;
#pragma unroll
        for (int s = 1; s < 16; s <<= 1) {
            ps += __shfl_xor_sync(0xffffffffu, ps, s);
            pd += __shfl_xor_sync(0xffffffffu, pd, s);
        }
        if (tx == 0) {
            int m = m0 + ty * 4 + ii;
            int bb = m >> 10, n = m & (NT - 1);
            esrc[((size_t)bb * NH + hh) * NT + n] = ps;
            edst[((size_t)bb * NH + hh) * NT + n] = pd;
        }
        float4 o;
        o.x = acc[ii][0]; o.y = acc[ii][1]; o.z = acc[ii][2]; o.w = acc[ii][3];
        *reinterpret_cast<float4*>(C + (size_t)(m0 + ty * 4 + ii) * HID + n0 + tx * 4) = o;
    }
}

// ---------------- mma.sync tf32 fused GAT attention (tw computed in staging) ----------------
// CTA = (head, batch, 128-row i-block), 256 threads, 8 warps x 16 rows.
// Single-pass softmax with a-priori bound m_i = max(es_i + max_j(ed_j), 0);
// P rounded to tf32; H split hi/lo (3xTF32-style).
#define ATTN_SMEM_FLOATS (128 * 36 + 2 * 32 * 72 + 1024 + 8)
__global__ void __launch_bounds__(256) k_attn(
    const float* __restrict__ gh, const float* __restrict__ esrc,
    const float* __restrict__ edst, const int* __restrict__ adj,
    const float* __restrict__ tm, float* __restrict__ nodeout, int nb) {
    extern __shared__ float sm[];
    float* tw_s  = sm;                     // [128][36]
    float* hhi_s = tw_s + 128 * 36;        // [32][72]
    float* hlo_s = hhi_s + 32 * 72;        // [32][72]
    float* edst_s = hlo_s + 32 * 72;       // [1024]
    float* red_s  = edst_s + 1024;         // [8]

    int t = threadIdx.x;
    int wid = t >> 5, lid = t & 31;
    int hh = blockIdx.x & 7;
    int rem = blockIdx.x >> 3;
    int b = rem & 7;
    int iblk = rem >> 3;
    int i0 = iblk * 128;
    int bh = (nb == 1) ? 0 : b;
    float tmax = __uint_as_float(g_tmax_u);

    // edst row -> smem, and its max
    const float* ed = edst + (size_t)(bh * NH + hh) * NT;
    float vmax = -1e30f;
    for (int u = t; u < NT; u += 256) { float v = ed[u]; edst_s[u] = v; vmax = fmaxf(vmax, v); }
#pragma unroll
    for (int s = 16; s; s >>= 1) vmax = fmaxf(vmax, __shfl_xor_sync(0xffffffffu, vmax, s));
    if (lid == 0) red_s[wid] = vmax;
    __syncthreads();
    float edmax = red_s[0];
#pragma unroll
    for (int w = 1; w < 8; w++) edmax = fmaxf(edmax, red_s[w]);

    int g = lid >> 2, q = lid & 3;
    int r0 = wid * 16 + g, r1 = r0 + 8;
    const float* esp = esrc + (size_t)(bh * NH + hh) * NT + i0;
    float es0 = esp[r0], es1 = esp[r1];
    float m0 = fmaxf(es0 + edmax, 0.f), m1 = fmaxf(es1 + edmax, 0.f);

    float acc[8][4] = {};
    float l0 = 0.f, l1 = 0.f;

    const float* tmbase  = tm  + ((size_t)b * NT + i0) * NT;
    const int*   adjbase = adj + ((size_t)b * NT + i0) * NT;
    const float* hbase   = gh + (size_t)bh * NT * HID + hh * HD;

    int srow = t >> 1, scol = (t & 1) * 16;   // tw staging: 128 rows x 32 cols
    int hrow = t >> 3, hcol = (t & 7) * 8;    // h staging: 32 rows x 64 cols

    for (int T = 0; T < NT / 32; T++) {
        int j0 = T * 32;
        // ---- stage tw tile [128 i][32 j]: tw = adj ? exp(-0.1*(tmax-t)) : -1 ----
        {
            const float* tp = tmbase + (size_t)srow * NT + j0 + scol;
            const int*  apx = adjbase + (size_t)srow * NT + j0 + scol;
            float* td = tw_s + srow * 36 + scol;
#pragma unroll
            for (int qq = 0; qq < 4; qq++) {
                float4 v = *reinterpret_cast<const float4*>(tp + qq * 4);
                int4  a  = *reinterpret_cast<const int4*>(apx + qq * 4);
                float4 o;
                o.x = a.x ? __expf(-0.1f * (tmax - v.x)) : -1.f;
                o.y = a.y ? __expf(-0.1f * (tmax - v.y)) : -1.f;
                o.z = a.z ? __expf(-0.1f * (tmax - v.z)) : -1.f;
                o.w = a.w ? __expf(-0.1f * (tmax - v.w)) : -1.f;
                *reinterpret_cast<float4*>(td + qq * 4) = o;
            }
        }
        // ---- stage h tile [32 j][64 d], tf32 hi/lo split ----
        {
            const float* hp = hbase + (size_t)(j0 + hrow) * HID + hcol;
            float4 a = *reinterpret_cast<const float4*>(hp);
            float4 c = *reinterpret_cast<const float4*>(hp + 4);
            float4 ahi, alo, chi, clo;
            ahi.x = tf32r(a.x); alo.x = tf32r(a.x - ahi.x);
            ahi.y = tf32r(a.y); alo.y = tf32r(a.y - ahi.y);
            ahi.z = tf32r(a.z); alo.z = tf32r(a.z - ahi.z);
            ahi.w = tf32r(a.w); alo.w = tf32r(a.w - ahi.w);
            chi.x = tf32r(c.x); clo.x = tf32r(c.x - chi.x);
            chi.y = tf32r(c.y); clo.y = tf32r(c.y - chi.y);
            chi.z = tf32r(c.z); clo.z = tf32r(c.z - chi.z);
            chi.w = tf32r(c.w); clo.w = tf32r(c.w - chi.w);
            float* dh = hhi_s + hrow * 72 + hcol;
            float* dl = hlo_s + hrow * 72 + hcol;
            *reinterpret_cast<float4*>(dh)     = ahi;
            *reinterpret_cast<float4*>(dh + 4) = chi;
            *reinterpret_cast<float4*>(dl)     = alo;
            *reinterpret_cast<float4*>(dl + 4) = clo;
        }
        __syncthreads();

#pragma unroll
        for (int kc = 0; kc < 4; kc++) {
            int c0 = kc * 8 + q, c1 = c0 + 4;
            float ed0 = edst_s[j0 + c0], ed1 = edst_s[j0 + c1];
            float tw00 = tw_s[r0 * 36 + c0], tw01 = tw_s[r0 * 36 + c1];
            float tw10 = tw_s[r1 * 36 + c0], tw11 = tw_s[r1 * 36 + c1];
            float x, lk;
            x = es0 + ed0; lk = fmaxf(x, 0.2f * x);
            float p00 = (tw00 < 0.f) ? 0.f : tf32r(__expf(lk * tw00 - m0));
            x = es0 + ed1; lk = fmaxf(x, 0.2f * x);
            float p01 = (tw01 < 0.f) ? 0.f : tf32r(__expf(lk * tw01 - m0));
            x = es1 + ed0; lk = fmaxf(x, 0.2f * x);
            float p10 = (tw10 < 0.f) ? 0.f : tf32r(__expf(lk * tw10 - m1));
            x = es1 + ed1; lk = fmaxf(x, 0.2f * x);
            float p11 = (tw11 < 0.f) ? 0.f : tf32r(__expf(lk * tw11 - m1));
            l0 += p00 + p01;
            l1 += p10 + p11;
            uint32_t A0 = __float_as_uint(p00), A1 = __float_as_uint(p10);
            uint32_t A2 = __float_as_uint(p01), A3 = __float_as_uint(p11);
            const float* bh0p = hhi_s + c0 * 72 + g;
            const float* bh1p = hhi_s + c1 * 72 + g;
            const float* bl0p = hlo_s + c0 * 72 + g;
            const float* bl1p = hlo_s + c1 * 72 + g;
#pragma unroll
            for (int nbk = 0; nbk < 8; nbk++) {
                uint32_t b0 = __float_as_uint(bh0p[nbk * 8]);
                uint32_t b1 = __float_as_uint(bh1p[nbk * 8]);
                mma_tf32(acc[nbk], A0, A1, A2, A3, b0, b1);
                uint32_t b2 = __float_as_uint(bl0p[nbk * 8]);
                uint32_t b3 = __float_as_uint(bl1p[nbk * 8]);
                mma_tf32(acc[nbk], A0, A1, A2, A3, b2, b3);
            }
        }
        __syncthreads();
    }

    // reduce l within quads (lanes sharing the same rows)
    l0 += __shfl_xor_sync(0xffffffffu, l0, 1);
    l0 += __shfl_xor_sync(0xffffffffu, l0, 2);
    l1 += __shfl_xor_sync(0xffffffffu, l1, 1);
    l1 += __shfl_xor_sync(0xffffffffu, l1, 2);
    float inv0 = 1.f / l0, inv1 = 1.f / l1;

    // epilogue: elu(acc/l) straight from fragments
    float* o0 = nodeout + ((size_t)b * NT + i0 + r0) * HID + hh * HD;
    float* o1 = nodeout + ((size_t)b * NT + i0 + r1) * HID + hh * HD;
#pragma unroll
    for (int nbk = 0; nbk < 8; nbk++) {
        int col = nbk * 8 + q * 2;
        float v0 = acc[nbk][0] * inv0, v1 = acc[nbk][1] * inv0;
        float v2 = acc[nbk][2] * inv1, v3 = acc[nbk][3] * inv1;
        float2 w0, w1;
        w0.x = v0 > 0.f ? v0 : (__expf(v0) - 1.f);
        w0.y = v1 > 0.f ? v1 : (__expf(v1) - 1.f);
        w1.x = v2 > 0.f ? v2 : (__expf(v2) - 1.f);
        w1.y = v3 > 0.f ? v3 : (__expf(v3) - 1.f);
        *reinterpret_cast<float2*>(o0 + col) = w0;
        *reinterpret_cast<float2*>(o1 + col) = w1;
    }
}

// ---------------- final MLP ----------------
__global__ void k_final(const float* __restrict__ node, const int* __restrict__ topic_ids,
                        const float* __restrict__ attractiveness,
                        const float* __restrict__ aW, const float* __restrict__ ab,
                        const float* __restrict__ f1W, const float* __restrict__ f1b,
                        const float* __restrict__ f2W, const float* __restrict__ f2b,
                        float* __restrict__ out) {
    int b = blockIdx.x;
    int t = threadIdx.x;  // 512
    __shared__ float comb[HID];
    __shared__ float red[16];
    int tid = topic_ids[b];
    float av = attractiveness[b];
    comb[t] = node[((size_t)b * NT + tid) * HID + t] + av * aW[t] + ab[t];
    __syncthreads();
    float acc = f1b[t];
    const float4* w = reinterpret_cast<const float4*>(f1W + (size_t)t * HID);
    const float4* c4 = reinterpret_cast<const float4*>(comb);
#pragma unroll 8
    for (int o = 0; o < HID / 4; o++) {
        float4 wv = w[o], cv = c4[o];
        acc += wv.x * cv.x + wv.y * cv.y + wv.z * cv.z + wv.w * cv.w;
    }
    acc = fmaxf(acc, 0.f);
    float p = acc * f2W[t];
#pragma unroll
    for (int s = 16; s; s >>= 1) p += __shfl_xor_sync(0xffffffffu, p, s);
    if ((t & 31) == 0) red[t >> 5] = p;
    __syncthreads();
    if (t < 16) {
        float v = red[t];
#pragma unroll
        for (int s = 8; s; s >>= 1) v += __shfl_xor_sync(0xffffu, v, s);
        if (t == 0) out[b] = v + f2b[0];
    }
}

// ---------------- launch ----------------
extern "C" void kernel_launch(void* const* d_in, const int* in_sizes, int n_in,
                              void* d_out, int out_size) {
    const int*   topic_ids = (const int*)d_in[0];
    const int*   adj       = (const int*)d_in[1];
    const float* timem     = (const float*)d_in[2];
    const float* attract   = (const float*)d_in[3];
    const float* emb       = (const float*)d_in[4];
    const float* sW        = (const float*)d_in[5];
    const float* sb        = (const float*)d_in[6];
    const float* aW        = (const float*)d_in[7];
    const float* ab        = (const float*)d_in[8];
    const float* gW        = (const float*)d_in[9];
    const float* ga        = (const float*)d_in[10];
    const float* f1W       = (const float*)d_in[11];
    const float* f1b       = (const float*)d_in[12];
    const float* f2W       = (const float*)d_in[13];
    const float* f2b       = (const float*)d_in[14];
    float* out = (float*)d_out;

    void *pv;
    cudaGetSymbolAddress(&pv, g_weff); float* weff = (float*)pv;
    cudaGetSymbolAddress(&pv, g_beff); float* beff = (float*)pv;
    cudaGetSymbolAddress(&pv, g_h);    float* h    = (float*)pv;
    cudaGetSymbolAddress(&pv, g_node); float* node = (float*)pv;
    cudaGetSymbolAddress(&pv, g_esrc); float* esrc = (float*)pv;
    cudaGetSymbolAddress(&pv, g_edst); float* edst = (float*)pv;

    const int attn_smem = ATTN_SMEM_FLOATS * (int)sizeof(float);  // ~41KB
    cudaFuncSetAttribute(k_attn, cudaFuncAttributeMaxDynamicSharedMemorySize, attn_smem);

    int n4 = (BATCH * NT * NT) / 4;

    // 1: tmax
    k_tmax<<<2048, 256>>>(reinterpret_cast<const float4*>(timem), n4);
    // 2: Weff/beff (fuses struct GEMM into layer-0 weights)
    k_weff<<<dim3(TD / 64, HID / 64), 256>>>(sW, sb, gW, weff, beff);
    // 3: h0 = emb @ Weff + beff, fused esrc/edst (batch-invariant, nb=1)
    k_gemmse<<<dim3(NT / 64, HID / 64), 256>>>(emb, weff, h, beff, TD, 0, ga, esrc, edst);
    // 4: attention layer 0  (<- ncu capture slot)
    k_attn<<<BATCH * NH * (NT / 128), 256, attn_smem>>>(h, esrc, edst, adj, timem, node, 1);
    // 5: h1 = node @ W1cat (direct gat_W indexing), fused esrc/edst
    k_gemmse<<<dim3(BATCH * NT / 64, HID / 64), 256>>>(node, gW + (size_t)NH * HID * HD, h,
                                                       nullptr, HID, 1, ga + (size_t)NH * 2 * HD,
                                                       esrc, edst);
    // 6: attention layer 1
    k_attn<<<BATCH * NH * (NT / 128), 256, attn_smem>>>(h, esrc, edst, adj, timem, node, BATCH);
    // 7: final MLP
    k_final<<<BATCH, 512>>>(node, topic_ids, attract, aW, ab, f1W, f1b, f2W, f2b, out);
}

// round 7
// speedup vs baseline: 1.3183x; 1.3183x over previous
#include <cuda_runtime.h>
#include <math.h>
#include <stddef.h>
#include <stdint.h>

#define BATCH 8
#define NT 1024
#define TD 128
#define HID 512
#define NH 8
#define HD 64
#define LOG2E 1.4426950408889634f

// ---------------- helpers ----------------
__device__ __forceinline__ float tf32r(float x){
    uint32_t u; asm("cvt.rna.tf32.f32 %0, %1;" : "=r"(u) : "f"(x));
    return __uint_as_float(u);
}
__device__ __forceinline__ float ex2f(float x){
    float r; asm("ex2.approx.f32 %0, %1;" : "=f"(r) : "f"(x));
    return r;
}
__device__ __forceinline__ void mma_tf32(float* c,
    uint32_t a0, uint32_t a1, uint32_t a2, uint32_t a3,
    uint32_t b0, uint32_t b1){
    asm("mma.sync.aligned.m16n8k8.row.col.f32.tf32.tf32.f32 "
        "{%0,%1,%2,%3}, {%4,%5,%6,%7}, {%8,%9}, {%0,%1,%2,%3};"
        : "+f"(c[0]), "+f"(c[1]), "+f"(c[2]), "+f"(c[3])
        : "r"(a0), "r"(a1), "r"(a2), "r"(a3), "r"(b0), "r"(b1));
}

// ---------------- device scratch (static; no allocation) ----------------
__device__ unsigned g_tmax_u;                 // zero at load; atomicMax idempotent across replays
__device__ float g_twm[BATCH * NT * NT];      // adj ? exp(-0.1*(tmax-t))*log2e : -1
__device__ float g_weff[TD * HID];            // struct_W^T @ W0cat
__device__ float g_beff[HID];                 // struct_b @ W0cat
__device__ float g_h[BATCH * NT * HID];       // h per (b,n,[h*64+d])
__device__ float g_node[BATCH * NT * HID];    // GAT layer output
__device__ float g_esrc[BATCH * NH * NT];
__device__ float g_edst[BATCH * NH * NT];

// ---------------- tmax ----------------
__global__ void k_tmax(const float4* __restrict__ t, int n4) {
    float m = 0.f;
    for (int i = blockIdx.x * blockDim.x + threadIdx.x; i < n4; i += gridDim.x * blockDim.x) {
        float4 v = t[i];
        m = fmaxf(m, fmaxf(fmaxf(v.x, v.y), fmaxf(v.z, v.w)));
    }
#pragma unroll
    for (int s = 16; s; s >>= 1) m = fmaxf(m, __shfl_xor_sync(0xffffffffu, m, s));
    __shared__ float sm[8];
    if ((threadIdx.x & 31) == 0) sm[threadIdx.x >> 5] = m;
    __syncthreads();
    if (threadIdx.x == 0) {
        for (int w = 1; w < 8; w++) m = fmaxf(m, sm[w]);
        atomicMax(&g_tmax_u, __float_as_uint(m));
    }
}

// ---------------- twm: tw' = adj ? exp(-0.1*(tmax-t))*log2e : -1 ----------------
__global__ void k_twm(const float4* __restrict__ tm, const int4* __restrict__ adj, int n4) {
    float tmax = __uint_as_float(g_tmax_u);
    int stride = gridDim.x * blockDim.x;
    for (int i = blockIdx.x * blockDim.x + threadIdx.x; i < n4; i += stride) {
        float4 t = tm[i];
        int4 a = adj[i];
        float4 o;
        o.x = a.x ? __expf(-0.1f * (tmax - t.x)) * LOG2E : -1.f;
        o.y = a.y ? __expf(-0.1f * (tmax - t.y)) * LOG2E : -1.f;
        o.z = a.z ? __expf(-0.1f * (tmax - t.z)) * LOG2E : -1.f;
        o.w = a.w ? __expf(-0.1f * (tmax - t.w)) * LOG2E : -1.f;
        reinterpret_cast<float4*>(g_twm)[i] = o;
    }
}

// ---------------- Weff = struct_W^T @ W0cat ; beff = struct_b @ W0cat ----------------
__global__ void k_weff(const float* __restrict__ sW, const float* __restrict__ sb,
                       const float* __restrict__ gW0,
                       float* __restrict__ weff, float* __restrict__ beff) {
    __shared__ float As[32][68];
    __shared__ float Bs[32][68];
    int t = threadIdx.x;
    int tx = t & 15, ty = t >> 4;
    int m0 = blockIdx.x * 64, n0 = blockIdx.y * 64;
    int hh = n0 >> 6;
    const float* B0 = gW0 + (size_t)hh * (HID * HD);
    float acc[4][4] = {};
    int bk = t >> 3, bnc = (t & 7) * 8;

    for (int kt = 0; kt < HID; kt += 32) {
        {
            const float* ap = sW + (size_t)(kt + bk) * TD + m0 + bnc;
            *reinterpret_cast<float4*>(&As[bk][bnc])     = *reinterpret_cast<const float4*>(ap);
            *reinterpret_cast<float4*>(&As[bk][bnc + 4]) = *reinterpret_cast<const float4*>(ap + 4);
            const float* bp = B0 + (size_t)(kt + bk) * HD + bnc;
            *reinterpret_cast<float4*>(&Bs[bk][bnc])     = *reinterpret_cast<const float4*>(bp);
            *reinterpret_cast<float4*>(&Bs[bk][bnc + 4]) = *reinterpret_cast<const float4*>(bp + 4);
        }
        __syncthreads();
#pragma unroll
        for (int k = 0; k < 32; k++) {
            float4 a4 = *reinterpret_cast<const float4*>(&As[k][ty * 4]);
            float4 b4 = *reinterpret_cast<const float4*>(&Bs[k][tx * 4]);
            acc[0][0] += a4.x * b4.x; acc[0][1] += a4.x * b4.y; acc[0][2] += a4.x * b4.z; acc[0][3] += a4.x * b4.w;
            acc[1][0] += a4.y * b4.x; acc[1][1] += a4.y * b4.y; acc[1][2] += a4.y * b4.z; acc[1][3] += a4.y * b4.w;
            acc[2][0] += a4.z * b4.x; acc[2][1] += a4.z * b4.y; acc[2][2] += a4.z * b4.z; acc[2][3] += a4.z * b4.w;
            acc[3][0] += a4.w * b4.x; acc[3][1] += a4.w * b4.y; acc[3][2] += a4.w * b4.z; acc[3][3] += a4.w * b4.w;
        }
        __syncthreads();
    }
#pragma unroll
    for (int ii = 0; ii < 4; ii++) {
        float4 o;
        o.x = acc[ii][0]; o.y = acc[ii][1]; o.z = acc[ii][2]; o.w = acc[ii][3];
        *reinterpret_cast<float4*>(weff + (size_t)(m0 + ty * 4 + ii) * HID + n0 + tx * 4) = o;
    }
    if (blockIdx.x == 0 && t < 64) {
        float s = 0.f;
        for (int k = 0; k < HID; k++) s += sb[k] * B0[(size_t)k * HD + t];
        beff[n0 + t] = s;
    }
}

// ---------------- 64x64 fp32 GEMM + fused e_src/e_dst epilogue ----------------
__global__ void k_gemmse(const float* __restrict__ A, const float* __restrict__ B,
                         float* __restrict__ C, const float* __restrict__ bias,
                         int K, int bgat, const float* __restrict__ ga,
                         float* __restrict__ esrc, float* __restrict__ edst) {
    __shared__ float As[32][68];
    __shared__ float Bs[32][68];
    int t = threadIdx.x;
    int tx = t & 15, ty = t >> 4;
    int m0 = blockIdx.x * 64, n0 = blockIdx.y * 64;
    int hh = n0 >> 6;
    float acc[4][4] = {};
    int ar = t >> 3, akc = (t & 7) * 4;
    int bk = t >> 3, bnc = (t & 7) * 8;
    const float* Bbase = bgat ? (B + (size_t)hh * (HID * HD)) : (B + n0);
    int bstride = bgat ? HD : HID;

    for (int kt = 0; kt < K; kt += 32) {
#pragma unroll
        for (int rr = 0; rr < 64; rr += 32) {
            float4 v = *reinterpret_cast<const float4*>(A + (size_t)(m0 + ar + rr) * K + kt + akc);
            As[akc + 0][ar + rr] = v.x;
            As[akc + 1][ar + rr] = v.y;
            As[akc + 2][ar + rr] = v.z;
            As[akc + 3][ar + rr] = v.w;
        }
        {
            const float* bp = Bbase + (size_t)(kt + bk) * bstride + bnc;
            *reinterpret_cast<float4*>(&Bs[bk][bnc])     = *reinterpret_cast<const float4*>(bp);
            *reinterpret_cast<float4*>(&Bs[bk][bnc + 4]) = *reinterpret_cast<const float4*>(bp + 4);
        }
        __syncthreads();
#pragma unroll
        for (int k = 0; k < 32; k++) {
            float4 a4 = *reinterpret_cast<const float4*>(&As[k][ty * 4]);
            float4 b4 = *reinterpret_cast<const float4*>(&Bs[k][tx * 4]);
            acc[0][0] += a4.x * b4.x; acc[0][1] += a4.x * b4.y; acc[0][2] += a4.x * b4.z; acc[0][3] += a4.x * b4.w;
            acc[1][0] += a4.y * b4.x; acc[1][1] += a4.y * b4.y; acc[1][2] += a4.y * b4.z; acc[1][3] += a4.y * b4.w;
            acc[2][0] += a4.z * b4.x; acc[2][1] += a4.z * b4.y; acc[2][2] += a4.z * b4.z; acc[2][3] += a4.z * b4.w;
            acc[3][0] += a4.w * b4.x; acc[3][1] += a4.w * b4.y; acc[3][2] += a4.w * b4.z; acc[3][3] += a4.w * b4.w;
        }
        __syncthreads();
    }
    if (bias) {
        float bx = bias[n0 + tx * 4 + 0], by = bias[n0 + tx * 4 + 1];
        float bz = bias[n0 + tx * 4 + 2], bw = bias[n0 + tx * 4 + 3];
#pragma unroll
        for (int ii = 0; ii < 4; ii++) {
            acc[ii][0] += bx; acc[ii][1] += by; acc[ii][2] += bz; acc[ii][3] += bw;
        }
    }
    const float* gas = ga + (size_t)hh * 2 * HD;
    float as0 = gas[tx * 4 + 0], as1 = gas[tx * 4 + 1], as2 = gas[tx * 4 + 2], as3 = gas[tx * 4 + 3];
    float ad0 = gas[HD + tx * 4 + 0], ad1 = gas[HD + tx * 4 + 1], ad2 = gas[HD + tx * 4 + 2], ad3 = gas[HD + tx * 4 + 3];
#pragma unroll
    for (int ii = 0; ii < 4; ii++) {
        float ps = acc[ii][0] * as0 + acc[ii][1] * as1 + acc[ii][2] * as2 + acc[ii][3] * as3;
        float pd = acc[ii][0] * ad0 + acc[ii][1] * ad1 + acc[ii][2] * ad2 + acc[ii][3] * ad3;
#pragma unroll
        for (int s = 1; s < 16; s <<= 1) {
            ps += __shfl_xor_sync(0xffffffffu, ps, s);
            pd += __shfl_xor_sync(0xffffffffu, pd, s);
        }
        if (tx == 0) {
            int m = m0 + ty * 4 + ii;
            int bb = m >> 10, n = m & (NT - 1);
            esrc[((size_t)bb * NH + hh) * NT + n] = ps;
            edst[((size_t)bb * NH + hh) * NT + n] = pd;
        }
        float4 o;
        o.x = acc[ii][0]; o.y = acc[ii][1]; o.z = acc[ii][2]; o.w = acc[ii][3];
        *reinterpret_cast<float4*>(C + (size_t)(m0 + ty * 4 + ii) * HID + n0 + tx * 4) = o;
    }
}

// ---------------- mma.sync tf32 fused GAT attention, 32 rows/warp ----------------
// CTA = (head, batch, 128-row i-block), 128 threads (4 warps x 32 rows).
// Single-pass softmax with a-priori bound; P rna-rounded (l matches MMA);
// H single tf32; twm precomputed with log2e folded; reg-prefetch pipeline.
#define ATTN_SMEM_FLOATS (128 * 36 + 32 * 72 + 1024 + 8)
__global__ void __launch_bounds__(128) k_attn(
    const float* __restrict__ gh, const float* __restrict__ esrc,
    const float* __restrict__ edst, const float* __restrict__ twm,
    float* __restrict__ nodeout, int nb) {
    extern __shared__ float sm[];
    float* tw_s   = sm;                    // [128][36]
    float* h_s    = tw_s + 128 * 36;       // [32][72]
    float* edst_s = h_s + 32 * 72;         // [1024]
    float* red_s  = edst_s + 1024;         // [4]

    int t = threadIdx.x;
    int wid = t >> 5, lid = t & 31;
    int hh = blockIdx.x & 7;
    int rem = blockIdx.x >> 3;
    int b = rem & 7;
    int iblk = rem >> 3;
    int i0 = iblk * 128;
    int bh = (nb == 1) ? 0 : b;

    // edst row -> smem, and its max
    const float* ed = edst + (size_t)(bh * NH + hh) * NT;
    float vmax = -1e30f;
#pragma unroll
    for (int u = 0; u < 8; u++) {
        float v = ed[t + u * 128]; edst_s[t + u * 128] = v; vmax = fmaxf(vmax, v);
    }
#pragma unroll
    for (int s = 16; s; s >>= 1) vmax = fmaxf(vmax, __shfl_xor_sync(0xffffffffu, vmax, s));
    if (lid == 0) red_s[wid] = vmax;
    __syncthreads();
    float edmax = fmaxf(fmaxf(red_s[0], red_s[1]), fmaxf(red_s[2], red_s[3]));

    int g = lid >> 2, q = lid & 3;
    int rbase = wid * 32 + g;              // rows rbase + {0,8,16,24}
    const float* esp = esrc + (size_t)(bh * NH + hh) * NT + i0;
    float es_r[4], m_r[4], l_r[4];
#pragma unroll
    for (int k = 0; k < 4; k++) {
        es_r[k] = esp[rbase + k * 8];
        m_r[k] = fmaxf((es_r[k] + edmax) * LOG2E, 0.f);
        l_r[k] = 0.f;
    }

    float acc[2][8][4] = {};

    const float* twb = twm + ((size_t)b * NT + i0 + t) * NT;   // this thread's staging row
    const float* hb  = gh + (size_t)bh * NT * HID + hh * HD;
    int hrow = t >> 2, hcol = (t & 3) * 16;

    // prefetch tile 0
    float4 twr[8], hraw[4];
#pragma unroll
    for (int k = 0; k < 8; k++) twr[k] = *reinterpret_cast<const float4*>(twb + k * 4);
    {
        const float* hp = hb + (size_t)hrow * HID + hcol;
#pragma unroll
        for (int k = 0; k < 4; k++) hraw[k] = *reinterpret_cast<const float4*>(hp + k * 4);
    }

    const float* twrowp = tw_s + (size_t)rbase * 36;

    for (int T = 0; T < 32; T++) {
        int j0 = T * 32;
        __syncthreads();   // prior tile's reads complete
        // store staged tile
        {
            float* td = tw_s + t * 36;
#pragma unroll
            for (int k = 0; k < 8; k++) *reinterpret_cast<float4*>(td + k * 4) = twr[k];
            float* dh = h_s + hrow * 72 + hcol;
#pragma unroll
            for (int k = 0; k < 4; k++) {
                float4 v = hraw[k];
                float4 o;
                o.x = tf32r(v.x); o.y = tf32r(v.y); o.z = tf32r(v.z); o.w = tf32r(v.w);
                *reinterpret_cast<float4*>(dh + k * 4) = o;
            }
        }
        // prefetch next tile
        if (T < 31) {
            const float* tp = twb + j0 + 32;
#pragma unroll
            for (int k = 0; k < 8; k++) twr[k] = *reinterpret_cast<const float4*>(tp + k * 4);
            const float* hp = hb + (size_t)(j0 + 32 + hrow) * HID + hcol;
#pragma unroll
            for (int k = 0; k < 4; k++) hraw[k] = *reinterpret_cast<const float4*>(hp + k * 4);
        }
        __syncthreads();   // staged tile visible

#pragma unroll
        for (int kc = 0; kc < 4; kc++) {
            int c0 = kc * 8 + q;
            float ed0 = edst_s[j0 + c0], ed1 = edst_s[j0 + c0 + 4];
            uint32_t Af[2][4];
#pragma unroll
            for (int x = 0; x < 2; x++) {
#pragma unroll
                for (int sub = 0; sub < 2; sub++) {
                    int k4 = x * 2 + sub;
                    const float* twp = twrowp + (x * 16 + sub * 8) * 36;
                    float tw0 = twp[c0], tw1 = twp[c0 + 4];
                    float es = es_r[k4], mp = m_r[k4];
                    float xx = es + ed0;
                    float lk = fmaxf(xx, 0.2f * xx);
                    float p0 = ex2f(fmaf(lk, tw0, -mp));
                    p0 = (tw0 < 0.f) ? 0.f : tf32r(p0);
                    xx = es + ed1;
                    lk = fmaxf(xx, 0.2f * xx);
                    float p1 = ex2f(fmaf(lk, tw1, -mp));
                    p1 = (tw1 < 0.f) ? 0.f : tf32r(p1);
                    l_r[k4] += p0 + p1;
                    Af[x][sub]     = __float_as_uint(p0);
                    Af[x][sub + 2] = __float_as_uint(p1);
                }
            }
            const float* bp0 = h_s + (size_t)c0 * 72 + g;
            const float* bp1 = bp0 + 4 * 72;
#pragma unroll
            for (int nbk = 0; nbk < 8; nbk++) {
                uint32_t b0 = __float_as_uint(bp0[nbk * 8]);
                uint32_t b1 = __float_as_uint(bp1[nbk * 8]);
                mma_tf32(acc[0][nbk], Af[0][0], Af[0][1], Af[0][2], Af[0][3], b0, b1);
                mma_tf32(acc[1][nbk], Af[1][0], Af[1][1], Af[1][2], Af[1][3], b0, b1);
            }
        }
    }

    // reduce l within quads
    float inv[4];
#pragma unroll
    for (int k = 0; k < 4; k++) {
        float l = l_r[k];
        l += __shfl_xor_sync(0xffffffffu, l, 1);
        l += __shfl_xor_sync(0xffffffffu, l, 2);
        inv[k] = 1.f / l;
    }

    // epilogue: elu(acc/l)
#pragma unroll
    for (int x = 0; x < 2; x++) {
        int rA = wid * 32 + x * 16 + g;
        float* oA = nodeout + ((size_t)b * NT + i0 + rA) * HID + hh * HD;
        float* oB = oA + (size_t)8 * HID;
        float iA = inv[x * 2 + 0], iB = inv[x * 2 + 1];
#pragma unroll
        for (int nbk = 0; nbk < 8; nbk++) {
            int col = nbk * 8 + q * 2;
            float v0 = acc[x][nbk][0] * iA, v1 = acc[x][nbk][1] * iA;
            float v2 = acc[x][nbk][2] * iB, v3 = acc[x][nbk][3] * iB;
            float2 w0, w1;
            w0.x = v0 > 0.f ? v0 : (__expf(v0) - 1.f);
            w0.y = v1 > 0.f ? v1 : (__expf(v1) - 1.f);
            w1.x = v2 > 0.f ? v2 : (__expf(v2) - 1.f);
            w1.y = v3 > 0.f ? v3 : (__expf(v3) - 1.f);
            *reinterpret_cast<float2*>(oA + col) = w0;
            *reinterpret_cast<float2*>(oB + col) = w1;
        }
    }
}

// ---------------- final MLP ----------------
__global__ void k_final(const float* __restrict__ node, const int* __restrict__ topic_ids,
                        const float* __restrict__ attractiveness,
                        const float* __restrict__ aW, const float* __restrict__ ab,
                        const float* __restrict__ f1W, const float* __restrict__ f1b,
                        const float* __restrict__ f2W, const float* __restrict__ f2b,
                        float* __restrict__ out) {
    int b = blockIdx.x;
    int t = threadIdx.x;  // 512
    __shared__ float comb[HID];
    __shared__ float red[16];
    int tid = topic_ids[b];
    float av = attractiveness[b];
    comb[t] = node[((size_t)b * NT + tid) * HID + t] + av * aW[t] + ab[t];
    __syncthreads();
    float acc = f1b[t];
    const float4* w = reinterpret_cast<const float4*>(f1W + (size_t)t * HID);
    const float4* c4 = reinterpret_cast<const float4*>(comb);
#pragma unroll 8
    for (int o = 0; o < HID / 4; o++) {
        float4 wv = w[o], cv = c4[o];
        acc += wv.x * cv.x + wv.y * cv.y + wv.z * cv.z + wv.w * cv.w;
    }
    acc = fmaxf(acc, 0.f);
    float p = acc * f2W[t];
#pragma unroll
    for (int s = 16; s; s >>= 1) p += __shfl_xor_sync(0xffffffffu, p, s);
    if ((t & 31) == 0) red[t >> 5] = p;
    __syncthreads();
    if (t < 16) {
        float v = red[t];
#pragma unroll
        for (int s = 8; s; s >>= 1) v += __shfl_xor_sync(0xffffu, v, s);
        if (t == 0) out[b] = v + f2b[0];
    }
}

// ---------------- launch ----------------
extern "C" void kernel_launch(void* const* d_in, const int* in_sizes, int n_in,
                              void* d_out, int out_size) {
    const int*   topic_ids = (const int*)d_in[0];
    const int*   adj       = (const int*)d_in[1];
    const float* timem     = (const float*)d_in[2];
    const float* attract   = (const float*)d_in[3];
    const float* emb       = (const float*)d_in[4];
    const float* sW        = (const float*)d_in[5];
    const float* sb        = (const float*)d_in[6];
    const float* aW        = (const float*)d_in[7];
    const float* ab        = (const float*)d_in[8];
    const float* gW        = (const float*)d_in[9];
    const float* ga        = (const float*)d_in[10];
    const float* f1W       = (const float*)d_in[11];
    const float* f1b       = (const float*)d_in[12];
    const float* f2W       = (const float*)d_in[13];
    const float* f2b       = (const float*)d_in[14];
    float* out = (float*)d_out;

    void *pv;
    cudaGetSymbolAddress(&pv, g_twm);  float* twm  = (float*)pv;
    cudaGetSymbolAddress(&pv, g_weff); float* weff = (float*)pv;
    cudaGetSymbolAddress(&pv, g_beff); float* beff = (float*)pv;
    cudaGetSymbolAddress(&pv, g_h);    float* h    = (float*)pv;
    cudaGetSymbolAddress(&pv, g_node); float* node = (float*)pv;
    cudaGetSymbolAddress(&pv, g_esrc); float* esrc = (float*)pv;
    cudaGetSymbolAddress(&pv, g_edst); float* edst = (float*)pv;

    const int attn_smem = ATTN_SMEM_FLOATS * (int)sizeof(float);  // ~32KB
    cudaFuncSetAttribute(k_attn, cudaFuncAttributeMaxDynamicSharedMemorySize, attn_smem);

    int n4 = (BATCH * NT * NT) / 4;

    // 1: tmax
    k_tmax<<<2048, 256>>>(reinterpret_cast<const float4*>(timem), n4);
    // 2: twm precompute (log2e folded)
    k_twm<<<4096, 256>>>(reinterpret_cast<const float4*>(timem),
                         reinterpret_cast<const int4*>(adj), n4);
    // 3: Weff/beff
    k_weff<<<dim3(TD / 64, HID / 64), 256>>>(sW, sb, gW, weff, beff);
    // 4: h0 = emb @ Weff + beff, fused esrc/edst  (<- ncu capture slot)
    k_gemmse<<<dim3(NT / 64, HID / 64), 256>>>(emb, weff, h, beff, TD, 0, ga, esrc, edst);
    // 5: attention layer 0
    k_attn<<<BATCH * NH * (NT / 128), 128, attn_smem>>>(h, esrc, edst, twm, node, 1);
    // 6: h1 = node @ W1cat, fused esrc/edst
    k_gemmse<<<dim3(BATCH * NT / 64, HID / 64), 256>>>(node, gW + (size_t)NH * HID * HD, h,
                                                       nullptr, HID, 1, ga + (size_t)NH * 2 * HD,
                                                       esrc, edst);
    // 7: attention layer 1
    k_attn<<<BATCH * NH * (NT / 128), 128, attn_smem>>>(h, esrc, edst, twm, node, BATCH);
    // 8: final MLP
    k_final<<<BATCH, 512>>>(node, topic_ids, attract, aW, ab, f1W, f1b, f2W, f2b, out);
}

// round 8
// speedup vs baseline: 1.7430x; 1.3222x over previous
#include <cuda_runtime.h>
#include <math.h>
#include <stddef.h>
#include <stdint.h>

#define BATCH 8
#define NT 1024
#define TD 128
#define HID 512
#define NH 8
#define HD 64
#define LOG2E 1.4426950408889634f

// ---------------- helpers ----------------
__device__ __forceinline__ float tf32r(float x){
    uint32_t u; asm("cvt.rna.tf32.f32 %0, %1;" : "=r"(u) : "f"(x));
    return __uint_as_float(u);
}
__device__ __forceinline__ float ex2f(float x){
    float r; asm("ex2.approx.f32 %0, %1;" : "=f"(r) : "f"(x));
    return r;
}
__device__ __forceinline__ void mma_tf32(float* c,
    uint32_t a0, uint32_t a1, uint32_t a2, uint32_t a3,
    uint32_t b0, uint32_t b1){
    asm("mma.sync.aligned.m16n8k8.row.col.f32.tf32.tf32.f32 "
        "{%0,%1,%2,%3}, {%4,%5,%6,%7}, {%8,%9}, {%0,%1,%2,%3};"
        : "+f"(c[0]), "+f"(c[1]), "+f"(c[2]), "+f"(c[3])
        : "r"(a0), "r"(a1), "r"(a2), "r"(a3), "r"(b0), "r"(b1));
}

// ---------------- device scratch (static; no allocation) ----------------
__device__ unsigned g_tmax_u;                 // zero at load; atomicMax idempotent across replays
__device__ float g_twm[BATCH * NT * NT];      // adj ? exp(0.1*t)*log2e : -1   (tmax-independent!)
__device__ float g_weff[TD * HID];            // struct_W^T @ W0cat
__device__ float g_beff[HID];                 // struct_b @ W0cat
__device__ float g_h[BATCH * NT * HID];       // h per (b,n,[h*64+d])
__device__ float g_node[BATCH * NT * HID];    // GAT layer output
__device__ float g_esrc[BATCH * NH * NT];
__device__ float g_edst[BATCH * NH * NT];

// ---------------- twm + tmax fused (twm no longer depends on tmax) ----------------
__global__ void k_twm(const float4* __restrict__ tm, const int4* __restrict__ adj, int n4) {
    float m = 0.f;
    int stride = gridDim.x * blockDim.x;
    for (int i = blockIdx.x * blockDim.x + threadIdx.x; i < n4; i += stride) {
        float4 t = tm[i];
        int4 a = adj[i];
        float4 o;
        o.x = a.x ? __expf(0.1f * t.x) * LOG2E : -1.f;
        o.y = a.y ? __expf(0.1f * t.y) * LOG2E : -1.f;
        o.z = a.z ? __expf(0.1f * t.z) * LOG2E : -1.f;
        o.w = a.w ? __expf(0.1f * t.w) * LOG2E : -1.f;
        reinterpret_cast<float4*>(g_twm)[i] = o;
        m = fmaxf(m, fmaxf(fmaxf(t.x, t.y), fmaxf(t.z, t.w)));
    }
#pragma unroll
    for (int s = 16; s; s >>= 1) m = fmaxf(m, __shfl_xor_sync(0xffffffffu, m, s));
    __shared__ float sm[8];
    if ((threadIdx.x & 31) == 0) sm[threadIdx.x >> 5] = m;
    __syncthreads();
    if (threadIdx.x == 0) {
        for (int w = 1; w < 8; w++) m = fmaxf(m, sm[w]);
        atomicMax(&g_tmax_u, __float_as_uint(m));   // t >= 0: uint order == float order
    }
}

// ---------------- Weff = struct_W^T @ W0cat ; beff = struct_b @ W0cat ----------------
__global__ void k_weff(const float* __restrict__ sW, const float* __restrict__ sb,
                       const float* __restrict__ gW0,
                       float* __restrict__ weff, float* __restrict__ beff) {
    __shared__ float As[32][68];
    __shared__ float Bs[32][68];
    int t = threadIdx.x;
    int tx = t & 15, ty = t >> 4;
    int m0 = blockIdx.x * 64, n0 = blockIdx.y * 64;
    int hh = n0 >> 6;
    const float* B0 = gW0 + (size_t)hh * (HID * HD);
    float acc[4][4] = {};
    int bk = t >> 3, bnc = (t & 7) * 8;

    for (int kt = 0; kt < HID; kt += 32) {
        {
            const float* ap = sW + (size_t)(kt + bk) * TD + m0 + bnc;
            *reinterpret_cast<float4*>(&As[bk][bnc])     = *reinterpret_cast<const float4*>(ap);
            *reinterpret_cast<float4*>(&As[bk][bnc + 4]) = *reinterpret_cast<const float4*>(ap + 4);
            const float* bp = B0 + (size_t)(kt + bk) * HD + bnc;
            *reinterpret_cast<float4*>(&Bs[bk][bnc])     = *reinterpret_cast<const float4*>(bp);
            *reinterpret_cast<float4*>(&Bs[bk][bnc + 4]) = *reinterpret_cast<const float4*>(bp + 4);
        }
        __syncthreads();
#pragma unroll
        for (int k = 0; k < 32; k++) {
            float4 a4 = *reinterpret_cast<const float4*>(&As[k][ty * 4]);
            float4 b4 = *reinterpret_cast<const float4*>(&Bs[k][tx * 4]);
            acc[0][0] += a4.x * b4.x; acc[0][1] += a4.x * b4.y; acc[0][2] += a4.x * b4.z; acc[0][3] += a4.x * b4.w;
            acc[1][0] += a4.y * b4.x; acc[1][1] += a4.y * b4.y; acc[1][2] += a4.y * b4.z; acc[1][3] += a4.y * b4.w;
            acc[2][0] += a4.z * b4.x; acc[2][1] += a4.z * b4.y; acc[2][2] += a4.z * b4.z; acc[2][3] += a4.z * b4.w;
            acc[3][0] += a4.w * b4.x; acc[3][1] += a4.w * b4.y; acc[3][2] += a4.w * b4.z; acc[3][3] += a4.w * b4.w;
        }
        __syncthreads();
    }
#pragma unroll
    for (int ii = 0; ii < 4; ii++) {
        float4 o;
        o.x = acc[ii][0]; o.y = acc[ii][1]; o.z = acc[ii][2]; o.w = acc[ii][3];
        *reinterpret_cast<float4*>(weff + (size_t)(m0 + ty * 4 + ii) * HID + n0 + tx * 4) = o;
    }
    if (blockIdx.x == 0 && t < 64) {
        float s = 0.f;
        for (int k = 0; k < HID; k++) s += sb[k] * B0[(size_t)k * HD + t];
        beff[n0 + t] = s;
    }
}

// ---------------- 64x64 fp32 GEMM + fused e_src/e_dst epilogue ----------------
__global__ void k_gemmse(const float* __restrict__ A, const float* __restrict__ B,
                         float* __restrict__ C, const float* __restrict__ bias,
                         int K, int bgat, const float* __restrict__ ga,
                         float* __restrict__ esrc, float* __restrict__ edst) {
    __shared__ float As[32][68];
    __shared__ float Bs[32][68];
    int t = threadIdx.x;
    int tx = t & 15, ty = t >> 4;
    int m0 = blockIdx.x * 64, n0 = blockIdx.y * 64;
    int hh = n0 >> 6;
    float acc[4][4] = {};
    int ar = t >> 3, akc = (t & 7) * 4;
    int bk = t >> 3, bnc = (t & 7) * 8;
    const float* Bbase = bgat ? (B + (size_t)hh * (HID * HD)) : (B + n0);
    int bstride = bgat ? HD : HID;

    for (int kt = 0; kt < K; kt += 32) {
#pragma unroll
        for (int rr = 0; rr < 64; rr += 32) {
            float4 v = *reinterpret_cast<const float4*>(A + (size_t)(m0 + ar + rr) * K + kt + akc);
            As[akc + 0][ar + rr] = v.x;
            As[akc + 1][ar + rr] = v.y;
            As[akc + 2][ar + rr] = v.z;
            As[akc + 3][ar + rr] = v.w;
        }
        {
            const float* bp = Bbase + (size_t)(kt + bk) * bstride + bnc;
            *reinterpret_cast<float4*>(&Bs[bk][bnc])     = *reinterpret_cast<const float4*>(bp);
            *reinterpret_cast<float4*>(&Bs[bk][bnc + 4]) = *reinterpret_cast<const float4*>(bp + 4);
        }
        __syncthreads();
#pragma unroll
        for (int k = 0; k < 32; k++) {
            float4 a4 = *reinterpret_cast<const float4*>(&As[k][ty * 4]);
            float4 b4 = *reinterpret_cast<const float4*>(&Bs[k][tx * 4]);
            acc[0][0] += a4.x * b4.x; acc[0][1] += a4.x * b4.y; acc[0][2] += a4.x * b4.z; acc[0][3] += a4.x * b4.w;
            acc[1][0] += a4.y * b4.x; acc[1][1] += a4.y * b4.y; acc[1][2] += a4.y * b4.z; acc[1][3] += a4.y * b4.w;
            acc[2][0] += a4.z * b4.x; acc[2][1] += a4.z * b4.y; acc[2][2] += a4.z * b4.z; acc[2][3] += a4.z * b4.w;
            acc[3][0] += a4.w * b4.x; acc[3][1] += a4.w * b4.y; acc[3][2] += a4.w * b4.z; acc[3][3] += a4.w * b4.w;
        }
        __syncthreads();
    }
    if (bias) {
        float bx = bias[n0 + tx * 4 + 0], by = bias[n0 + tx * 4 + 1];
        float bz = bias[n0 + tx * 4 + 2], bw = bias[n0 + tx * 4 + 3];
#pragma unroll
        for (int ii = 0; ii < 4; ii++) {
            acc[ii][0] += bx; acc[ii][1] += by; acc[ii][2] += bz; acc[ii][3] += bw;
        }
    }
    const float* gas = ga + (size_t)hh * 2 * HD;
    float as0 = gas[tx * 4 + 0], as1 = gas[tx * 4 + 1], as2 = gas[tx * 4 + 2], as3 = gas[tx * 4 + 3];
    float ad0 = gas[HD + tx * 4 + 0], ad1 = gas[HD + tx * 4 + 1], ad2 = gas[HD + tx * 4 + 2], ad3 = gas[HD + tx * 4 + 3];
#pragma unroll
    for (int ii = 0; ii < 4; ii++) {
        float ps = acc[ii][0] * as0 + acc[ii][1] * as1 + acc[ii][2] * as2 + acc[ii][3] * as3;
        float pd = acc[ii][0] * ad0 + acc[ii][1] * ad1 + acc[ii][2] * ad2 + acc[ii][3] * ad3;
#pragma unroll
        for (int s = 1; s < 16; s <<= 1) {
            ps += __shfl_xor_sync(0xffffffffu, ps, s);
            pd += __shfl_xor_sync(0xffffffffu, pd, s);
        }
        if (tx == 0) {
            int m = m0 + ty * 4 + ii;
            int bb = m >> 10, n = m & (NT - 1);
            esrc[((size_t)bb * NH + hh) * NT + n] = ps;
            edst[((size_t)bb * NH + hh) * NT + n] = pd;
        }
        float4 o;
        o.x = acc[ii][0]; o.y = acc[ii][1]; o.z = acc[ii][2]; o.w = acc[ii][3];
        *reinterpret_cast<float4*>(C + (size_t)(m0 + ty * 4 + ii) * HID + n0 + tx * 4) = o;
    }
}

// ---------------- mma.sync tf32 fused GAT attention ----------------
// CTA = (head, batch, 128-row i-block), 128 threads (4 warps x 32 rows).
// tw loaded DIRECTLY from gmem per fragment (each value used exactly once);
// H tile double-buffered in smem (1 sync/tile); es/ed pre-scaled by s = e^{-0.1 tmax}.
#define ATTN_SMEM_FLOATS (2 * 32 * 72 + 1024 + 8)
__global__ void __launch_bounds__(128) k_attn(
    const float* __restrict__ gh, const float* __restrict__ esrc,
    const float* __restrict__ edst, const float* __restrict__ twm,
    float* __restrict__ nodeout, int nb) {
    extern __shared__ float sm[];
    float* hs0    = sm;                    // [32][72]
    float* hs1    = hs0 + 32 * 72;         // [32][72]
    float* edst_s = hs1 + 32 * 72;         // [1024] (scaled by s)
    float* red_s  = edst_s + 1024;         // [4]

    int t = threadIdx.x;
    int wid = t >> 5, lid = t & 31;
    int hh = blockIdx.x & 7;
    int rem = blockIdx.x >> 3;
    int b = rem & 7;
    int iblk = rem >> 3;
    int i0 = iblk * 128;
    int bh = (nb == 1) ? 0 : b;

    float tmax = __uint_as_float(g_tmax_u);
    float s = __expf(-0.1f * tmax);

    // edst -> smem scaled; max over UNSCALED
    const float* ed = edst + (size_t)(bh * NH + hh) * NT;
    float vmax = -1e30f;
#pragma unroll
    for (int u = 0; u < 8; u++) {
        float v = ed[t + u * 128];
        edst_s[t + u * 128] = v * s;
        vmax = fmaxf(vmax, v);
    }
#pragma unroll
    for (int ss = 16; ss; ss >>= 1) vmax = fmaxf(vmax, __shfl_xor_sync(0xffffffffu, vmax, ss));
    if (lid == 0) red_s[wid] = vmax;
    __syncthreads();
    float edmax = fmaxf(fmaxf(red_s[0], red_s[1]), fmaxf(red_s[2], red_s[3]));

    int g = lid >> 2, q = lid & 3;
    int rbase = wid * 32 + g;              // rows rbase + {0,8,16,24}
    const float* esp = esrc + (size_t)(bh * NH + hh) * NT + i0;
    float es_s[4], m_r[4], l_r[4];
#pragma unroll
    for (int k = 0; k < 4; k++) {
        float esu = esp[rbase + k * 8];
        m_r[k] = fmaxf((esu + edmax) * LOG2E, 0.f);
        es_s[k] = esu * s;
        l_r[k] = 0.f;
    }

    float acc[2][8][4] = {};

    const float* twq = twm + ((size_t)(b * NT + i0 + rbase)) * NT + q;  // + k4*8*NT + j
    const float* hb  = gh + (size_t)bh * NT * HID + hh * HD;
    int hrow = t >> 2, hcol = (t & 3) * 16;

    // prologue: tile 0 -> hs0; prefetch tile 1
    float4 hraw[4];
    {
        const float* hp = hb + (size_t)hrow * HID + hcol;
#pragma unroll
        for (int k = 0; k < 4; k++) hraw[k] = *reinterpret_cast<const float4*>(hp + k * 4);
        float* dh = hs0 + hrow * 72 + hcol;
#pragma unroll
        for (int k = 0; k < 4; k++) {
            float4 v = hraw[k];
            float4 o;
            o.x = tf32r(v.x); o.y = tf32r(v.y); o.z = tf32r(v.z); o.w = tf32r(v.w);
            *reinterpret_cast<float4*>(dh + k * 4) = o;
        }
        const float* hp1 = hb + (size_t)(32 + hrow) * HID + hcol;
#pragma unroll
        for (int k = 0; k < 4; k++) hraw[k] = *reinterpret_cast<const float4*>(hp1 + k * 4);
    }
    __syncthreads();

    int cur = 0;
    for (int T = 0; T < 32; T++) {
        int j0 = T * 32;
        float* hnext = cur ? hs0 : hs1;
        const float* hcur = cur ? hs1 : hs0;
        if (T < 31) {   // stage tile T+1 into the other buffer (nobody reads it this iter)
            float* dh = hnext + hrow * 72 + hcol;
#pragma unroll
            for (int k = 0; k < 4; k++) {
                float4 v = hraw[k];
                float4 o;
                o.x = tf32r(v.x); o.y = tf32r(v.y); o.z = tf32r(v.z); o.w = tf32r(v.w);
                *reinterpret_cast<float4*>(dh + k * 4) = o;
            }
        }
        if (T < 30) {   // prefetch tile T+2
            const float* hp = hb + (size_t)(j0 + 64 + hrow) * HID + hcol;
#pragma unroll
            for (int k = 0; k < 4; k++) hraw[k] = *reinterpret_cast<const float4*>(hp + k * 4);
        }

#pragma unroll
        for (int kc = 0; kc < 4; kc++) {
            int c0 = kc * 8 + q;
            // direct gmem tw loads (each value used exactly once)
            float tw0[4], tw1[4];
#pragma unroll
            for (int k4 = 0; k4 < 4; k4++) {
                const float* p = twq + (size_t)k4 * 8 * NT + j0 + kc * 8;
                tw0[k4] = p[0];
                tw1[k4] = p[4];
            }
            float ed0 = edst_s[j0 + c0], ed1 = edst_s[j0 + c0 + 4];
            uint32_t Af[2][4];
#pragma unroll
            for (int x = 0; x < 2; x++) {
#pragma unroll
                for (int sub = 0; sub < 2; sub++) {
                    int k4 = x * 2 + sub;
                    float xx = es_s[k4] + ed0;
                    float lk = fmaxf(xx, 0.2f * xx);
                    float p0 = ex2f(fmaf(lk, tw0[k4], -m_r[k4]));
                    p0 = (tw0[k4] < 0.f) ? 0.f : tf32r(p0);
                    xx = es_s[k4] + ed1;
                    lk = fmaxf(xx, 0.2f * xx);
                    float p1 = ex2f(fmaf(lk, tw1[k4], -m_r[k4]));
                    p1 = (tw1[k4] < 0.f) ? 0.f : tf32r(p1);
                    l_r[k4] += p0 + p1;
                    Af[x][sub]     = __float_as_uint(p0);
                    Af[x][sub + 2] = __float_as_uint(p1);
                }
            }
            const float* bp0 = hcur + (size_t)c0 * 72 + g;
            const float* bp1 = bp0 + 4 * 72;
#pragma unroll
            for (int nbk = 0; nbk < 8; nbk++) {
                uint32_t b0 = __float_as_uint(bp0[nbk * 8]);
                uint32_t b1 = __float_as_uint(bp1[nbk * 8]);
                mma_tf32(acc[0][nbk], Af[0][0], Af[0][1], Af[0][2], Af[0][3], b0, b1);
                mma_tf32(acc[1][nbk], Af[1][0], Af[1][1], Af[1][2], Af[1][3], b0, b1);
            }
        }
        __syncthreads();
        cur ^= 1;
    }

    // reduce l within quads
    float inv[4];
#pragma unroll
    for (int k = 0; k < 4; k++) {
        float l = l_r[k];
        l += __shfl_xor_sync(0xffffffffu, l, 1);
        l += __shfl_xor_sync(0xffffffffu, l, 2);
        inv[k] = 1.f / l;
    }

    // epilogue: elu(acc/l)
#pragma unroll
    for (int x = 0; x < 2; x++) {
        int rA = wid * 32 + x * 16 + g;
        float* oA = nodeout + ((size_t)b * NT + i0 + rA) * HID + hh * HD;
        float* oB = oA + (size_t)8 * HID;
        float iA = inv[x * 2 + 0], iB = inv[x * 2 + 1];
#pragma unroll
        for (int nbk = 0; nbk < 8; nbk++) {
            int col = nbk * 8 + q * 2;
            float v0 = acc[x][nbk][0] * iA, v1 = acc[x][nbk][1] * iA;
            float v2 = acc[x][nbk][2] * iB, v3 = acc[x][nbk][3] * iB;
            float2 w0, w1;
            w0.x = v0 > 0.f ? v0 : (__expf(v0) - 1.f);
            w0.y = v1 > 0.f ? v1 : (__expf(v1) - 1.f);
            w1.x = v2 > 0.f ? v2 : (__expf(v2) - 1.f);
            w1.y = v3 > 0.f ? v3 : (__expf(v3) - 1.f);
            *reinterpret_cast<float2*>(oA + col) = w0;
            *reinterpret_cast<float2*>(oB + col) = w1;
        }
    }
}

// ---------------- final MLP ----------------
__global__ void k_final(const float* __restrict__ node, const int* __restrict__ topic_ids,
                        const float* __restrict__ attractiveness,
                        const float* __restrict__ aW, const float* __restrict__ ab,
                        const float* __restrict__ f1W, const float* __restrict__ f1b,
                        const float* __restrict__ f2W, const float* __restrict__ f2b,
                        float* __restrict__ out) {
    int b = blockIdx.x;
    int t = threadIdx.x;  // 512
    __shared__ float comb[HID];
    __shared__ float red[16];
    int tid = topic_ids[b];
    float av = attractiveness[b];
    comb[t] = node[((size_t)b * NT + tid) * HID + t] + av * aW[t] + ab[t];
    __syncthreads();
    float acc = f1b[t];
    const float4* w = reinterpret_cast<const float4*>(f1W + (size_t)t * HID);
    const float4* c4 = reinterpret_cast<const float4*>(comb);
#pragma unroll 8
    for (int o = 0; o < HID / 4; o++) {
        float4 wv = w[o], cv = c4[o];
        acc += wv.x * cv.x + wv.y * cv.y + wv.z * cv.z + wv.w * cv.w;
    }
    acc = fmaxf(acc, 0.f);
    float p = acc * f2W[t];
#pragma unroll
    for (int s = 16; s; s >>= 1) p += __shfl_xor_sync(0xffffffffu, p, s);
    if ((t & 31) == 0) red[t >> 5] = p;
    __syncthreads();
    if (t < 16) {
        float v = red[t];
#pragma unroll
        for (int s = 8; s; s >>= 1) v += __shfl_xor_sync(0xffffu, v, s);
        if (t == 0) out[b] = v + f2b[0];
    }
}

// ---------------- launch ----------------
extern "C" void kernel_launch(void* const* d_in, const int* in_sizes, int n_in,
                              void* d_out, int out_size) {
    const int*   topic_ids = (const int*)d_in[0];
    const int*   adj       = (const int*)d_in[1];
    const float* timem     = (const float*)d_in[2];
    const float* attract   = (const float*)d_in[3];
    const float* emb       = (const float*)d_in[4];
    const float* sW        = (const float*)d_in[5];
    const float* sb        = (const float*)d_in[6];
    const float* aW        = (const float*)d_in[7];
    const float* ab        = (const float*)d_in[8];
    const float* gW        = (const float*)d_in[9];
    const float* ga        = (const float*)d_in[10];
    const float* f1W       = (const float*)d_in[11];
    const float* f1b       = (const float*)d_in[12];
    const float* f2W       = (const float*)d_in[13];
    const float* f2b       = (const float*)d_in[14];
    float* out = (float*)d_out;

    void *pv;
    cudaGetSymbolAddress(&pv, g_twm);  float* twm  = (float*)pv;
    cudaGetSymbolAddress(&pv, g_weff); float* weff = (float*)pv;
    cudaGetSymbolAddress(&pv, g_beff); float* beff = (float*)pv;
    cudaGetSymbolAddress(&pv, g_h);    float* h    = (float*)pv;
    cudaGetSymbolAddress(&pv, g_node); float* node = (float*)pv;
    cudaGetSymbolAddress(&pv, g_esrc); float* esrc = (float*)pv;
    cudaGetSymbolAddress(&pv, g_edst); float* edst = (float*)pv;

    const int attn_smem = ATTN_SMEM_FLOATS * (int)sizeof(float);  // ~22.6KB
    cudaFuncSetAttribute(k_attn, cudaFuncAttributeMaxDynamicSharedMemorySize, attn_smem);

    int n4 = (BATCH * NT * NT) / 4;

    // 1: twm (+ tmax reduction, tw no longer depends on tmax)
    k_twm<<<4096, 256>>>(reinterpret_cast<const float4*>(timem),
                         reinterpret_cast<const int4*>(adj), n4);
    // 2: Weff/beff
    k_weff<<<dim3(TD / 64, HID / 64), 256>>>(sW, sb, gW, weff, beff);
    // 3: h0 = emb @ Weff + beff, fused esrc/edst
    k_gemmse<<<dim3(NT / 64, HID / 64), 256>>>(emb, weff, h, beff, TD, 0, ga, esrc, edst);
    // 4: attention layer 0  (<- ncu capture slot)
    k_attn<<<BATCH * NH * (NT / 128), 128, attn_smem>>>(h, esrc, edst, twm, node, 1);
    // 5: h1 = node @ W1cat, fused esrc/edst
    k_gemmse<<<dim3(BATCH * NT / 64, HID / 64), 256>>>(node, gW + (size_t)NH * HID * HD, h,
                                                       nullptr, HID, 1, ga + (size_t)NH * 2 * HD,
                                                       esrc, edst);
    // 6: attention layer 1
    k_attn<<<BATCH * NH * (NT / 128), 128, attn_smem>>>(h, esrc, edst, twm, node, BATCH);
    // 7: final MLP
    k_final<<<BATCH, 512>>>(node, topic_ids, attract, aW, ab, f1W, f1b, f2W, f2b, out);
}

// round 9
// speedup vs baseline: 2.4889x; 1.4279x over previous
#include <cuda_runtime.h>
#include <math.h>
#include <stddef.h>
#include <stdint.h>

#define BATCH 8
#define NT 1024
#define TD 128
#define HID 512
#define NH 8
#define HD 64
#define LOG2E 1.4426950408889634f

// ---------------- helpers ----------------
__device__ __forceinline__ float tf32r(float x){
    uint32_t u; asm("cvt.rna.tf32.f32 %0, %1;" : "=r"(u) : "f"(x));
    return __uint_as_float(u);
}
__device__ __forceinline__ float ex2f(float x){
    float r; asm("ex2.approx.f32 %0, %1;" : "=f"(r) : "f"(x));
    return r;
}
__device__ __forceinline__ void mma_tf32(float* c,
    uint32_t a0, uint32_t a1, uint32_t a2, uint32_t a3,
    uint32_t b0, uint32_t b1){
    asm("mma.sync.aligned.m16n8k8.row.col.f32.tf32.tf32.f32 "
        "{%0,%1,%2,%3}, {%4,%5,%6,%7}, {%8,%9}, {%0,%1,%2,%3};"
        : "+f"(c[0]), "+f"(c[1]), "+f"(c[2]), "+f"(c[3])
        : "r"(a0), "r"(a1), "r"(a2), "r"(a3), "r"(b0), "r"(b1));
}
__device__ __forceinline__ uint32_t smem_u32(const void* p){
    uint32_t a;
    asm("{ .reg .u64 t; cvta.to.shared.u64 t, %1; cvt.u32.u64 %0, t; }" : "=r"(a) : "l"(p));
    return a;
}
__device__ __forceinline__ void cp16(uint32_t dst, const void* src){
    asm volatile("cp.async.cg.shared.global [%0], [%1], 16;" :: "r"(dst), "l"(src));
}
__device__ __forceinline__ void cp_commit(){
    asm volatile("cp.async.commit_group;" ::: "memory");
}
__device__ __forceinline__ void cp_wait0(){
    asm volatile("cp.async.wait_group 0;" ::: "memory");
}

// ---------------- device scratch (static; no allocation) ----------------
__device__ unsigned g_tmax_u;                 // zero at load; atomicMax idempotent across replays
__device__ float g_twm[BATCH * NT * NT];      // adj ? exp(0.1*t)*log2e : -1  (tmax-independent)
__device__ float g_weff[TD * HID];            // struct_W^T @ W0cat
__device__ float g_beff[HID];                 // struct_b @ W0cat
__device__ float g_h[BATCH * NT * HID];       // h per (b,n,[h*64+d])
__device__ float g_node[BATCH * NT * HID];    // GAT layer output
__device__ float g_esrc[BATCH * NH * NT];
__device__ float g_edst[BATCH * NH * NT];

// ---------------- twm + tmax fused ----------------
__global__ void k_twm(const float4* __restrict__ tm, const int4* __restrict__ adj, int n4) {
    float m = 0.f;
    int stride = gridDim.x * blockDim.x;
    for (int i = blockIdx.x * blockDim.x + threadIdx.x; i < n4; i += stride) {
        float4 t = tm[i];
        int4 a = adj[i];
        float4 o;
        o.x = a.x ? __expf(0.1f * t.x) * LOG2E : -1.f;
        o.y = a.y ? __expf(0.1f * t.y) * LOG2E : -1.f;
        o.z = a.z ? __expf(0.1f * t.z) * LOG2E : -1.f;
        o.w = a.w ? __expf(0.1f * t.w) * LOG2E : -1.f;
        reinterpret_cast<float4*>(g_twm)[i] = o;
        m = fmaxf(m, fmaxf(fmaxf(t.x, t.y), fmaxf(t.z, t.w)));
    }
#pragma unroll
    for (int s = 16; s; s >>= 1) m = fmaxf(m, __shfl_xor_sync(0xffffffffu, m, s));
    __shared__ float sm[8];
    if ((threadIdx.x & 31) == 0) sm[threadIdx.x >> 5] = m;
    __syncthreads();
    if (threadIdx.x == 0) {
        for (int w = 1; w < 8; w++) m = fmaxf(m, sm[w]);
        atomicMax(&g_tmax_u, __float_as_uint(m));   // t >= 0: uint order == float order
    }
}

// ---------------- Weff = struct_W^T @ W0cat ; beff = struct_b @ W0cat ----------------
__global__ void k_weff(const float* __restrict__ sW, const float* __restrict__ sb,
                       const float* __restrict__ gW0,
                       float* __restrict__ weff, float* __restrict__ beff) {
    __shared__ float As[32][68];
    __shared__ float Bs[32][68];
    int t = threadIdx.x;
    int tx = t & 15, ty = t >> 4;
    int m0 = blockIdx.x * 64, n0 = blockIdx.y * 64;
    int hh = n0 >> 6;
    const float* B0 = gW0 + (size_t)hh * (HID * HD);
    float acc[4][4] = {};
    int bk = t >> 3, bnc = (t & 7) * 8;

    for (int kt = 0; kt < HID; kt += 32) {
        {
            const float* ap = sW + (size_t)(kt + bk) * TD + m0 + bnc;
            *reinterpret_cast<float4*>(&As[bk][bnc])     = *reinterpret_cast<const float4*>(ap);
            *reinterpret_cast<float4*>(&As[bk][bnc + 4]) = *reinterpret_cast<const float4*>(ap + 4);
            const float* bp = B0 + (size_t)(kt + bk) * HD + bnc;
            *reinterpret_cast<float4*>(&Bs[bk][bnc])     = *reinterpret_cast<const float4*>(bp);
            *reinterpret_cast<float4*>(&Bs[bk][bnc + 4]) = *reinterpret_cast<const float4*>(bp + 4);
        }
        __syncthreads();
#pragma unroll
        for (int k = 0; k < 32; k++) {
            float4 a4 = *reinterpret_cast<const float4*>(&As[k][ty * 4]);
            float4 b4 = *reinterpret_cast<const float4*>(&Bs[k][tx * 4]);
            acc[0][0] += a4.x * b4.x; acc[0][1] += a4.x * b4.y; acc[0][2] += a4.x * b4.z; acc[0][3] += a4.x * b4.w;
            acc[1][0] += a4.y * b4.x; acc[1][1] += a4.y * b4.y; acc[1][2] += a4.y * b4.z; acc[1][3] += a4.y * b4.w;
            acc[2][0] += a4.z * b4.x; acc[2][1] += a4.z * b4.y; acc[2][2] += a4.z * b4.z; acc[2][3] += a4.z * b4.w;
            acc[3][0] += a4.w * b4.x; acc[3][1] += a4.w * b4.y; acc[3][2] += a4.w * b4.z; acc[3][3] += a4.w * b4.w;
        }
        __syncthreads();
    }
#pragma unroll
    for (int ii = 0; ii < 4; ii++) {
        float4 o;
        o.x = acc[ii][0]; o.y = acc[ii][1]; o.z = acc[ii][2]; o.w = acc[ii][3];
        *reinterpret_cast<float4*>(weff + (size_t)(m0 + ty * 4 + ii) * HID + n0 + tx * 4) = o;
    }
    if (blockIdx.x == 0 && t < 64) {
        float s = 0.f;
        for (int k = 0; k < HID; k++) s += sb[k] * B0[(size_t)k * HD + t];
        beff[n0 + t] = s;
    }
}

// ---------------- HMMA tf32 GEMM (M-block 128, N=64=one head) + fused se ----------------
// A [M,K] row-major fp32 (HW-truncated to tf32). bgat=0: B rows stride HID at col n0;
// bgat=1: B = gW layer slab, rows stride HD. j-permuted k-order (cols q<->2q, q+4<->2q+1).
__global__ void __launch_bounds__(128) k_gmma(
    const float* __restrict__ A, const float* __restrict__ B,
    float* __restrict__ C, const float* __restrict__ bias,
    int K, int bgat, const float* __restrict__ ga,
    float* __restrict__ esrc, float* __restrict__ edst) {
    __shared__ float Bs[2][32 * 68];

    int t = threadIdx.x;
    int wid = t >> 5, lid = t & 31;
    int g = lid >> 2, q = lid & 3;
    int m0 = blockIdx.x * 128;
    int hh = blockIdx.y;
    int n0 = hh * 64;

    const float* Bsrc = bgat ? (B + (size_t)hh * (HID * HD)) : (B + n0);
    int bstride = bgat ? HD : HID;

    int brow = t >> 2, bcol = (t & 3) * 16;
    uint32_t bs_base = smem_u32(Bs);
    uint32_t dst_off = (uint32_t)(brow * 68 + bcol) * 4u;

    // prologue: tile 0 -> buf 0
    {
        const float* src = Bsrc + (size_t)brow * bstride + bcol;
#pragma unroll
        for (int c = 0; c < 4; c++) cp16(bs_base + dst_off + c * 16u, src + c * 4);
        cp_commit();
    }

    int rbase = wid * 32 + g;
    const float* Aq = A + (size_t)(m0 + rbase) * K + 2 * q;

    float acc[2][8][4] = {};
    int ntiles = K / 32;

    for (int T = 0; T < ntiles; T++) {
        int k0 = T * 32;
        cp_wait0();
        __syncthreads();
        if (T + 1 < ntiles) {
            uint32_t buf = (uint32_t)((T + 1) & 1) * (32u * 68u * 4u);
            const float* src = Bsrc + (size_t)(k0 + 32 + brow) * bstride + bcol;
#pragma unroll
            for (int c = 0; c < 4; c++) cp16(bs_base + buf + dst_off + c * 16u, src + c * 4);
            cp_commit();
        }
        const float* bs = Bs[T & 1];
#pragma unroll
        for (int kc = 0; kc < 4; kc++) {
            float2 a[4];
#pragma unroll
            for (int k4 = 0; k4 < 4; k4++)
                a[k4] = *reinterpret_cast<const float2*>(Aq + (size_t)k4 * 8 * K + k0 + kc * 8);
            uint32_t Af[2][4];
            Af[0][0] = __float_as_uint(a[0].x); Af[0][1] = __float_as_uint(a[1].x);
            Af[0][2] = __float_as_uint(a[0].y); Af[0][3] = __float_as_uint(a[1].y);
            Af[1][0] = __float_as_uint(a[2].x); Af[1][1] = __float_as_uint(a[3].x);
            Af[1][2] = __float_as_uint(a[2].y); Af[1][3] = __float_as_uint(a[3].y);
            const float* bp0 = bs + (kc * 8 + 2 * q) * 68 + g;
            const float* bp1 = bp0 + 68;
#pragma unroll
            for (int nbk = 0; nbk < 8; nbk++) {
                uint32_t b0 = __float_as_uint(bp0[nbk * 8]);
                uint32_t b1 = __float_as_uint(bp1[nbk * 8]);
                mma_tf32(acc[0][nbk], Af[0][0], Af[0][1], Af[0][2], Af[0][3], b0, b1);
                mma_tf32(acc[1][nbk], Af[1][0], Af[1][1], Af[1][2], Af[1][3], b0, b1);
            }
        }
    }

    // bias
    if (bias) {
#pragma unroll
        for (int nbk = 0; nbk < 8; nbk++) {
            float bv0 = bias[n0 + nbk * 8 + 2 * q];
            float bv1 = bias[n0 + nbk * 8 + 2 * q + 1];
#pragma unroll
            for (int x = 0; x < 2; x++) {
                acc[x][nbk][0] += bv0; acc[x][nbk][1] += bv1;
                acc[x][nbk][2] += bv0; acc[x][nbk][3] += bv1;
            }
        }
    }

    // fused se + store
    const float* gas = ga + (size_t)hh * 2 * HD;
    float as0[8], as1[8], ad0[8], ad1[8];
#pragma unroll
    for (int nbk = 0; nbk < 8; nbk++) {
        int col = nbk * 8 + 2 * q;
        as0[nbk] = gas[col];      as1[nbk] = gas[col + 1];
        ad0[nbk] = gas[HD + col]; ad1[nbk] = gas[HD + col + 1];
    }
#pragma unroll
    for (int x = 0; x < 2; x++) {
        int rA = m0 + wid * 32 + x * 16 + g;
        int rB = rA + 8;
        float psA = 0.f, pdA = 0.f, psB = 0.f, pdB = 0.f;
#pragma unroll
        for (int nbk = 0; nbk < 8; nbk++) {
            psA += acc[x][nbk][0] * as0[nbk] + acc[x][nbk][1] * as1[nbk];
            pdA += acc[x][nbk][0] * ad0[nbk] + acc[x][nbk][1] * ad1[nbk];
            psB += acc[x][nbk][2] * as0[nbk] + acc[x][nbk][3] * as1[nbk];
            pdB += acc[x][nbk][2] * ad0[nbk] + acc[x][nbk][3] * ad1[nbk];
        }
#pragma unroll
        for (int s = 1; s < 4; s <<= 1) {
            psA += __shfl_xor_sync(0xffffffffu, psA, s);
            pdA += __shfl_xor_sync(0xffffffffu, pdA, s);
            psB += __shfl_xor_sync(0xffffffffu, psB, s);
            pdB += __shfl_xor_sync(0xffffffffu, pdB, s);
        }
        if (q == 0) {
            int bbA = rA >> 10, nA = rA & (NT - 1);
            int bbB = rB >> 10, nB = rB & (NT - 1);
            esrc[((size_t)bbA * NH + hh) * NT + nA] = psA;
            edst[((size_t)bbA * NH + hh) * NT + nA] = pdA;
            esrc[((size_t)bbB * NH + hh) * NT + nB] = psB;
            edst[((size_t)bbB * NH + hh) * NT + nB] = pdB;
        }
        float* cA = C + (size_t)rA * HID + n0 + 2 * q;
        float* cB = C + (size_t)rB * HID + n0 + 2 * q;
#pragma unroll
        for (int nbk = 0; nbk < 8; nbk++) {
            *reinterpret_cast<float2*>(cA + nbk * 8) = make_float2(acc[x][nbk][0], acc[x][nbk][1]);
            *reinterpret_cast<float2*>(cB + nbk * 8) = make_float2(acc[x][nbk][2], acc[x][nbk][3]);
        }
    }
}

// ---------------- mma.sync tf32 fused GAT attention ----------------
// CTA = (head, batch, 128-row i-block), 128 threads (4 warps x 32 rows).
// j-permuted k-order: mma col q <-> phys j 2q, col q+4 <-> 2q+1 within each 8-group
// => tw via LDG.64, conflict-free B-frag LDS (stride 68). H tile: cp.async double buffer,
// no CVT (HMMA truncates to tf32; P is explicitly rna-rounded so l stays consistent).
__global__ void __launch_bounds__(128) k_attn(
    const float* __restrict__ gh, const float* __restrict__ esrc,
    const float* __restrict__ edst, const float* __restrict__ twm,
    float* __restrict__ nodeout, int nb) {
    __shared__ float hs[2][32 * 68];
    __shared__ float edst_s[1024];
    __shared__ float red_s[4];

    int t = threadIdx.x;
    int wid = t >> 5, lid = t & 31;
    int hh = blockIdx.x & 7;
    int rem = blockIdx.x >> 3;
    int b = rem & 7;
    int iblk = rem >> 3;
    int i0 = iblk * 128;
    int bh = (nb == 1) ? 0 : b;

    float tmax = __uint_as_float(g_tmax_u);
    float s = __expf(-0.1f * tmax);

    const float* hb = gh + (size_t)bh * NT * HID + hh * HD;
    int hrow = t >> 2, hcol = (t & 3) * 16;
    uint32_t hs_base = smem_u32(hs);
    uint32_t dst_off = (uint32_t)(hrow * 68 + hcol) * 4u;

    // prologue: H tile 0 -> buf 0
    {
        const float* src = hb + (size_t)hrow * HID + hcol;
#pragma unroll
        for (int c = 0; c < 4; c++) cp16(hs_base + dst_off + c * 16u, src + c * 4);
        cp_commit();
    }

    // edst -> smem scaled; max over UNSCALED
    const float* ed = edst + (size_t)(bh * NH + hh) * NT;
    float vmax = -1e30f;
#pragma unroll
    for (int u = 0; u < 8; u++) {
        float v = ed[t + u * 128];
        edst_s[t + u * 128] = v * s;
        vmax = fmaxf(vmax, v);
    }
#pragma unroll
    for (int ss = 16; ss; ss >>= 1) vmax = fmaxf(vmax, __shfl_xor_sync(0xffffffffu, vmax, ss));
    if (lid == 0) red_s[wid] = vmax;
    __syncthreads();
    float edmax = fmaxf(fmaxf(red_s[0], red_s[1]), fmaxf(red_s[2], red_s[3]));

    int g = lid >> 2, q = lid & 3;
    int rbase = wid * 32 + g;
    const float* esp = esrc + (size_t)(bh * NH + hh) * NT + i0;
    float es_s[4], m_r[4], l_r[4];
#pragma unroll
    for (int k = 0; k < 4; k++) {
        float esu = esp[rbase + k * 8];
        m_r[k] = fmaxf((esu + edmax) * LOG2E, 0.f);
        es_s[k] = esu * s;
        l_r[k] = 0.f;
    }

    float acc[2][8][4] = {};
    const float* twq = twm + ((size_t)(b * NT + i0 + rbase)) * NT + 2 * q;

    for (int T = 0; T < 32; T++) {
        int j0 = T * 32;
        cp_wait0();
        __syncthreads();
        if (T < 31) {
            uint32_t buf = (uint32_t)((T + 1) & 1) * (32u * 68u * 4u);
            const float* src = hb + (size_t)(j0 + 32 + hrow) * HID + hcol;
#pragma unroll
            for (int c = 0; c < 4; c++) cp16(hs_base + buf + dst_off + c * 16u, src + c * 4);
            cp_commit();
        }
        const float* hcur = hs[T & 1];

#pragma unroll
        for (int kc = 0; kc < 4; kc++) {
            int jc = j0 + kc * 8 + 2 * q;
            float2 twv[4];
#pragma unroll
            for (int k4 = 0; k4 < 4; k4++)
                twv[k4] = *reinterpret_cast<const float2*>(twq + (size_t)k4 * 8 * NT + j0 + kc * 8);
            float ed0 = edst_s[jc], ed1 = edst_s[jc + 1];
            uint32_t Af[2][4];
#pragma unroll
            for (int x = 0; x < 2; x++) {
#pragma unroll
                for (int sub = 0; sub < 2; sub++) {
                    int k4 = x * 2 + sub;
                    float tw0 = twv[k4].x, tw1 = twv[k4].y;
                    float xx = es_s[k4] + ed0;
                    float lk = fmaxf(xx, 0.2f * xx);
                    float p0 = ex2f(fmaf(lk, tw0, -m_r[k4]));
                    p0 = (tw0 < 0.f) ? 0.f : tf32r(p0);
                    xx = es_s[k4] + ed1;
                    lk = fmaxf(xx, 0.2f * xx);
                    float p1 = ex2f(fmaf(lk, tw1, -m_r[k4]));
                    p1 = (tw1 < 0.f) ? 0.f : tf32r(p1);
                    l_r[k4] += p0 + p1;
                    Af[x][sub]     = __float_as_uint(p0);
                    Af[x][sub + 2] = __float_as_uint(p1);
                }
            }
            const float* bp0 = hcur + (kc * 8 + 2 * q) * 68 + g;
            const float* bp1 = bp0 + 68;
#pragma unroll
            for (int nbk = 0; nbk < 8; nbk++) {
                uint32_t b0 = __float_as_uint(bp0[nbk * 8]);
                uint32_t b1 = __float_as_uint(bp1[nbk * 8]);
                mma_tf32(acc[0][nbk], Af[0][0], Af[0][1], Af[0][2], Af[0][3], b0, b1);
                mma_tf32(acc[1][nbk], Af[1][0], Af[1][1], Af[1][2], Af[1][3], b0, b1);
            }
        }
    }

    // reduce l within quads
    float inv[4];
#pragma unroll
    for (int k = 0; k < 4; k++) {
        float l = l_r[k];
        l += __shfl_xor_sync(0xffffffffu, l, 1);
        l += __shfl_xor_sync(0xffffffffu, l, 2);
        inv[k] = 1.f / l;
    }

    // epilogue: elu(acc/l)
#pragma unroll
    for (int x = 0; x < 2; x++) {
        int rA = wid * 32 + x * 16 + g;
        float* oA = nodeout + ((size_t)b * NT + i0 + rA) * HID + hh * HD + 2 * q;
        float* oB = oA + (size_t)8 * HID;
        float iA = inv[x * 2 + 0], iB = inv[x * 2 + 1];
#pragma unroll
        for (int nbk = 0; nbk < 8; nbk++) {
            float v0 = acc[x][nbk][0] * iA, v1 = acc[x][nbk][1] * iA;
            float v2 = acc[x][nbk][2] * iB, v3 = acc[x][nbk][3] * iB;
            float2 w0, w1;
            w0.x = v0 > 0.f ? v0 : (__expf(v0) - 1.f);
            w0.y = v1 > 0.f ? v1 : (__expf(v1) - 1.f);
            w1.x = v2 > 0.f ? v2 : (__expf(v2) - 1.f);
            w1.y = v3 > 0.f ? v3 : (__expf(v3) - 1.f);
            *reinterpret_cast<float2*>(oA + nbk * 8) = w0;
            *reinterpret_cast<float2*>(oB + nbk * 8) = w1;
        }
    }
}

// ---------------- final MLP ----------------
__global__ void k_final(const float* __restrict__ node, const int* __restrict__ topic_ids,
                        const float* __restrict__ attractiveness,
                        const float* __restrict__ aW, const float* __restrict__ ab,
                        const float* __restrict__ f1W, const float* __restrict__ f1b,
                        const float* __restrict__ f2W, const float* __restrict__ f2b,
                        float* __restrict__ out) {
    int b = blockIdx.x;
    int t = threadIdx.x;  // 512
    __shared__ float comb[HID];
    __shared__ float red[16];
    int tid = topic_ids[b];
    float av = attractiveness[b];
    comb[t] = node[((size_t)b * NT + tid) * HID + t] + av * aW[t] + ab[t];
    __syncthreads();
    float acc = f1b[t];
    const float4* w = reinterpret_cast<const float4*>(f1W + (size_t)t * HID);
    const float4* c4 = reinterpret_cast<const float4*>(comb);
#pragma unroll 8
    for (int o = 0; o < HID / 4; o++) {
        float4 wv = w[o], cv = c4[o];
        acc += wv.x * cv.x + wv.y * cv.y + wv.z * cv.z + wv.w * cv.w;
    }
    acc = fmaxf(acc, 0.f);
    float p = acc * f2W[t];
#pragma unroll
    for (int s = 16; s; s >>= 1) p += __shfl_xor_sync(0xffffffffu, p, s);
    if ((t & 31) == 0) red[t >> 5] = p;
    __syncthreads();
    if (t < 16) {
        float v = red[t];
#pragma unroll
        for (int s = 8; s; s >>= 1) v += __shfl_xor_sync(0xffffu, v, s);
        if (t == 0) out[b] = v + f2b[0];
    }
}

// ---------------- launch ----------------
extern "C" void kernel_launch(void* const* d_in, const int* in_sizes, int n_in,
                              void* d_out, int out_size) {
    const int*   topic_ids = (const int*)d_in[0];
    const int*   adj       = (const int*)d_in[1];
    const float* timem     = (const float*)d_in[2];
    const float* attract   = (const float*)d_in[3];
    const float* emb       = (const float*)d_in[4];
    const float* sW        = (const float*)d_in[5];
    const float* sb        = (const float*)d_in[6];
    const float* aW        = (const float*)d_in[7];
    const float* ab        = (const float*)d_in[8];
    const float* gW        = (const float*)d_in[9];
    const float* ga        = (const float*)d_in[10];
    const float* f1W       = (const float*)d_in[11];
    const float* f1b       = (const float*)d_in[12];
    const float* f2W       = (const float*)d_in[13];
    const float* f2b       = (const float*)d_in[14];
    float* out = (float*)d_out;

    void *pv;
    cudaGetSymbolAddress(&pv, g_twm);  float* twm  = (float*)pv;
    cudaGetSymbolAddress(&pv, g_weff); float* weff = (float*)pv;
    cudaGetSymbolAddress(&pv, g_beff); float* beff = (float*)pv;
    cudaGetSymbolAddress(&pv, g_h);    float* h    = (float*)pv;
    cudaGetSymbolAddress(&pv, g_node); float* node = (float*)pv;
    cudaGetSymbolAddress(&pv, g_esrc); float* esrc = (float*)pv;
    cudaGetSymbolAddress(&pv, g_edst); float* edst = (float*)pv;

    int n4 = (BATCH * NT * NT) / 4;

    // 1: twm (+ tmax)
    k_twm<<<4096, 256>>>(reinterpret_cast<const float4*>(timem),
                         reinterpret_cast<const int4*>(adj), n4);
    // 2: Weff/beff
    k_weff<<<dim3(TD / 64, HID / 64), 256>>>(sW, sb, gW, weff, beff);
    // 3: h0 = emb @ Weff + beff (HMMA), fused esrc/edst
    k_gmma<<<dim3(NT / 128, NH), 128>>>(emb, weff, h, beff, TD, 0, ga, esrc, edst);
    // 4: attention layer 0  (<- ncu capture slot)
    k_attn<<<BATCH * NH * (NT / 128), 128>>>(h, esrc, edst, twm, node, 1);
    // 5: h1 = node @ W1cat (HMMA), fused esrc/edst
    k_gmma<<<dim3(BATCH * NT / 128, NH), 128>>>(node, gW + (size_t)NH * HID * HD, h,
                                                nullptr, HID, 1, ga + (size_t)NH * 2 * HD,
                                                esrc, edst);
    // 6: attention layer 1
    k_attn<<<BATCH * NH * (NT / 128), 128>>>(h, esrc, edst, twm, node, BATCH);
    // 7: final MLP
    k_final<<<BATCH, 512>>>(node, topic_ids, attract, aW, ab, f1W, f1b, f2W, f2b, out);
}